// round 4
// baseline (speedup 1.0000x reference)
#include <cuda_runtime.h>

// Per-channel 5x5 correlation, stride=1, pad=2; 128 planes of 512x512 f32.
// Register-rolling, one warp per CTA:
//   - warp owns a 256-wide x 16-row strip; lane owns 8 consecutive x.
//   - per input row: 2 aligned LDG.128 + 4 warp shuffles for the +-2 x halo
//     (warp-edge lanes do tiny predicated float2 gmem loads).
//   - each input row loaded ONCE, accumulated into 5 pending output rows in
//     registers (mod-5 rotation, compile-time via unroll-5 step blocks).
//   - packed f32x2 FMA: 100 FMA2 per row-step (8 outputs wide).
//   - packed weights live in SHARED memory (volatile reads -> stay out of
//     the register file; broadcast LDS.64, conflict-free).

#define IMG  512
#define R    16            // output rows per strip (per CTA)
#define FULLMASK 0xffffffffu

__device__ __forceinline__ unsigned long long pk(float lo, float hi) {
    unsigned long long r;
    asm("mov.b64 %0, {%1, %2};" : "=l"(r) : "f"(lo), "f"(hi));
    return r;
}
__device__ __forceinline__ void upk(unsigned long long v, float& lo, float& hi) {
    asm("mov.b64 {%0, %1}, %2;" : "=f"(lo), "=f"(hi) : "l"(v));
}
__device__ __forceinline__ unsigned long long fma2(unsigned long long a,
                                                   unsigned long long b,
                                                   unsigned long long c) {
    unsigned long long d;
    asm("fma.rn.f32x2 %0, %1, %2, %3;" : "=l"(d) : "l"(a), "l"(b), "l"(c));
    return d;
}

// All 25 taps of input-row (s) into the 5 pending output slots.
// I = s mod 5 (compile-time). Weights come from volatile smem (LDS.64 bcast).
template<int I>
__device__ __forceinline__ void accstep(unsigned long long acc[5][4],
                                        const volatile unsigned long long* wsm,
                                        const unsigned long long* __restrict__ p) {
    #pragma unroll
    for (int kr = 0; kr < 5; kr++) {
        const int slot = ((I - kr) % 5 + 5) % 5;   // compile-time after unroll
        #pragma unroll
        for (int t = 0; t < 5; t++) {
            const unsigned long long wv = wsm[kr * 5 + t];
            #pragma unroll
            for (int pj = 0; pj < 4; pj++)
                acc[slot][pj] = fma2(wv, p[2 * pj + t], acc[slot][pj]);
        }
    }
}

__global__ __launch_bounds__(32) void conv5x5_kernel(
    const float* __restrict__ X,
    const float* __restrict__ Kw,
    float* __restrict__ Out)
{
    __shared__ unsigned long long wsm[25];

    const int lane  = threadIdx.x;                  // 0..31
    const int c     = blockIdx.z;                   // plane
    const int warpX = blockIdx.x;                   // 0..1  (x half)
    const int strip = blockIdx.y;                   // 0..31 (y strip)
    const int Y0    = strip * R;
    const int x0    = warpX * 256 + lane * 8;

    const float* __restrict__ Xc = X   + (size_t)c * (IMG * IMG);
    float*       __restrict__ Oc = Out + (size_t)c * (IMG * IMG);

    // packed (w,w) weights -> shared
    if (lane < 25) {
        const float wv = __ldg(&Kw[lane]);
        wsm[lane] = pk(wv, wv);
    }
    __syncwarp();

    unsigned long long acc[5][4];
    #pragma unroll
    for (int j = 0; j < 5; j++)
        #pragma unroll
        for (int q = 0; q < 4; q++) acc[j][q] = 0ull;

    unsigned long long p[11];   // packed sliding-window pairs of current row

#define LOADROW(S, A, B, LF, RF) do {                                          \
    const int gy_ = Y0 - 2 + (S);                                              \
    (A) = make_float4(0.f,0.f,0.f,0.f); (B) = make_float4(0.f,0.f,0.f,0.f);    \
    (LF) = make_float2(0.f,0.f); (RF) = make_float2(0.f,0.f);                  \
    if ((unsigned)gy_ < (unsigned)IMG) {                                       \
        const float* rp_ = Xc + (size_t)gy_ * IMG + x0;                        \
        (A) = *reinterpret_cast<const float4*>(rp_);                           \
        (B) = *reinterpret_cast<const float4*>(rp_ + 4);                       \
        if (lane == 0  && x0 >= 2)      (LF) = *reinterpret_cast<const float2*>(rp_ - 2); \
        if (lane == 31 && x0 + 9 < IMG) (RF) = *reinterpret_cast<const float2*>(rp_ + 8); \
    }                                                                          \
} while (0)

#define PACKROW(A, B, LF, RF) do {                                             \
    float l0_ = __shfl_up_sync(FULLMASK,  (B).z, 1);                           \
    float l1_ = __shfl_up_sync(FULLMASK,  (B).w, 1);                           \
    float r0_ = __shfl_down_sync(FULLMASK,(A).x, 1);                           \
    float r1_ = __shfl_down_sync(FULLMASK,(A).y, 1);                           \
    if (lane == 0)  { l0_ = (LF).x; l1_ = (LF).y; }                            \
    if (lane == 31) { r0_ = (RF).x; r1_ = (RF).y; }                            \
    p[0]  = pk(l0_,  l1_ );  p[1]  = pk(l1_,  (A).x);                          \
    p[2]  = pk((A).x,(A).y); p[3]  = pk((A).y,(A).z);                          \
    p[4]  = pk((A).z,(A).w); p[5]  = pk((A).w,(B).x);                          \
    p[6]  = pk((B).x,(B).y); p[7]  = pk((B).y,(B).z);                          \
    p[8]  = pk((B).z,(B).w); p[9]  = pk((B).w, r0_ );                          \
    p[10] = pk(r0_,  r1_ );                                                    \
} while (0)

#define STEP(I, LAST) do {                                                     \
    const int s_ = sb + (I);                                                   \
    float4 A_, B_; float2 LF_, RF_;                                            \
    if (!(LAST)) LOADROW(s_ + 1, A_, B_, LF_, RF_);                            \
    accstep<(I)>(acc, wsm, p);                                                 \
    if ((I) >= 4 || sb >= 4) {                                                 \
        const int o_ = s_ - 4;                                                 \
        float r0,r1,r2,r3,r4,r5,r6,r7;                                         \
        upk(acc[((I)+1)%5][0], r0, r1);                                        \
        upk(acc[((I)+1)%5][1], r2, r3);                                        \
        upk(acc[((I)+1)%5][2], r4, r5);                                        \
        upk(acc[((I)+1)%5][3], r6, r7);                                        \
        float* op_ = Oc + (size_t)(Y0 + o_) * IMG + x0;                        \
        *reinterpret_cast<float4*>(op_)     = make_float4(r0,r1,r2,r3);        \
        *reinterpret_cast<float4*>(op_ + 4) = make_float4(r4,r5,r6,r7);        \
    }                                                                          \
    acc[((I)+1)%5][0] = 0ull; acc[((I)+1)%5][1] = 0ull;                        \
    acc[((I)+1)%5][2] = 0ull; acc[((I)+1)%5][3] = 0ull;                        \
    if (!(LAST)) PACKROW(A_, B_, LF_, RF_);                                    \
} while (0)

    // prologue: row 0 into p
    {
        float4 A0, B0; float2 LF0, RF0;
        LOADROW(0, A0, B0, LF0, RF0);
        PACKROW(A0, B0, LF0, RF0);
    }

    // steps 0..14 in unroll-5 blocks (R + 4 = 20 steps total)
    #pragma unroll 1
    for (int sb = 0; sb < 15; sb += 5) {
        STEP(0, false);
        STEP(1, false);
        STEP(2, false);
        STEP(3, false);
        STEP(4, false);
    }
    // final block sb = 15: steps 15..19, last one without prefetch
    {
        const int sb = 15;
        STEP(0, false);
        STEP(1, false);
        STEP(2, false);
        STEP(3, false);
        STEP(4, true);
    }

#undef STEP
#undef PACKROW
#undef LOADROW
}

extern "C" void kernel_launch(void* const* d_in, const int* in_sizes, int n_in,
                              void* d_out, int out_size)
{
    const float* X  = (const float*)d_in[0];
    const float* Kw = (const float*)d_in[1];
    float* Out      = (float*)d_out;

    dim3 grid(2, IMG / R, 128);   // 2 x-halves, 32 strips, 128 planes = 8192 CTAs
    dim3 block(32, 1);            // one warp per CTA
    conv5x5_kernel<<<grid, block>>>(X, Kw, Out);
}

// round 5
// speedup vs baseline: 1.4205x; 1.4205x over previous
#include <cuda_runtime.h>

// Per-channel 5x5 correlation, stride=1, pad=2; 128 planes of 512x512 f32.
// Register-rolling, 4 warps/CTA, warp owns a 256-wide x 16-row strip.
//   - per input row: 2 aligned LDG.128 + 4 warp shuffles for +-2 x halo.
//   - DEPTH-2 row prefetch (double-buffered raw regs, parity compile-time).
//   - each input row loaded ONCE, accumulated into 5 pending output rows in
//     registers (mod-5 rotation, compile-time via unroll-10 step blocks).
//   - packed f32x2 FMA: 100 FMA2 per row-step (8 outputs wide).

#define IMG  512
#define R    16
#define NSTEP (R + 4)      // 20 input rows per strip
#define FULLMASK 0xffffffffu

__device__ __forceinline__ unsigned long long pk(float lo, float hi) {
    unsigned long long r;
    asm("mov.b64 %0, {%1, %2};" : "=l"(r) : "f"(lo), "f"(hi));
    return r;
}
__device__ __forceinline__ void upk(unsigned long long v, float& lo, float& hi) {
    asm("mov.b64 {%0, %1}, %2;" : "=f"(lo), "=f"(hi) : "l"(v));
}
__device__ __forceinline__ unsigned long long fma2(unsigned long long a,
                                                   unsigned long long b,
                                                   unsigned long long c) {
    unsigned long long d;
    asm("fma.rn.f32x2 %0, %1, %2, %3;" : "=l"(d) : "l"(a), "l"(b), "l"(c));
    return d;
}

// All 25 taps of input-row (s) into the 5 pending output slots. I = s mod 5.
template<int I>
__device__ __forceinline__ void accstep(unsigned long long acc[5][4],
                                        const unsigned long long* __restrict__ wp,
                                        const unsigned long long* __restrict__ p) {
    #pragma unroll
    for (int kr = 0; kr < 5; kr++) {
        const int slot = ((I - kr) % 5 + 5) % 5;
        #pragma unroll
        for (int t = 0; t < 5; t++) {
            #pragma unroll
            for (int pj = 0; pj < 4; pj++)
                acc[slot][pj] = fma2(wp[kr * 5 + t], p[2 * pj + t], acc[slot][pj]);
        }
    }
}

__global__ __launch_bounds__(128, 5) void conv5x5_kernel(
    const float* __restrict__ X,
    const float* __restrict__ Kw,
    float* __restrict__ Out)
{
    const int lane  = threadIdx.x;
    const int wrp   = threadIdx.y;                  // 0..3
    const int c     = blockIdx.z;
    const int warpX = blockIdx.x;                   // 0..1
    const int strip = blockIdx.y * 4 + wrp;         // 0..31
    const int Y0    = strip * R;
    const int x0    = warpX * 256 + lane * 8;

    const float* __restrict__ Xc = X   + (size_t)c * (IMG * IMG);
    float*       __restrict__ Oc = Out + (size_t)c * (IMG * IMG);

    // packed (w,w) weights (warp-uniform -> UR promotion, as in R3)
    unsigned long long wp[25];
    #pragma unroll
    for (int i = 0; i < 25; i++) { const float wv = __ldg(&Kw[i]); wp[i] = pk(wv, wv); }

    unsigned long long acc[5][4];
    #pragma unroll
    for (int j = 0; j < 5; j++)
        #pragma unroll
        for (int q = 0; q < 4; q++) acc[j][q] = 0ull;

    unsigned long long p[11];
    float4 Ab[2], Bb[2];      // double-buffered raw rows
    float2 LFb[2], RFb[2];

// Load input row for step S into buffer PAR (zero outside image / past strip).
#define LOADROW(S, PAR) do {                                                   \
    const int s__ = (S);                                                       \
    const int gy_ = Y0 - 2 + s__;                                              \
    Ab[PAR] = make_float4(0.f,0.f,0.f,0.f); Bb[PAR] = make_float4(0.f,0.f,0.f,0.f); \
    LFb[PAR] = make_float2(0.f,0.f); RFb[PAR] = make_float2(0.f,0.f);          \
    if (s__ < NSTEP && (unsigned)gy_ < (unsigned)IMG) {                        \
        const float* rp_ = Xc + (size_t)gy_ * IMG + x0;                        \
        Ab[PAR] = *reinterpret_cast<const float4*>(rp_);                       \
        Bb[PAR] = *reinterpret_cast<const float4*>(rp_ + 4);                   \
        if (lane == 0  && x0 >= 2)      LFb[PAR] = *reinterpret_cast<const float2*>(rp_ - 2); \
        if (lane == 31 && x0 + 9 < IMG) RFb[PAR] = *reinterpret_cast<const float2*>(rp_ + 8); \
    }                                                                          \
} while (0)

// Shuffle halo + pack buffer PAR into p[0..10].
#define PACKROW(PAR) do {                                                      \
    float l0_ = __shfl_up_sync(FULLMASK,  Bb[PAR].z, 1);                       \
    float l1_ = __shfl_up_sync(FULLMASK,  Bb[PAR].w, 1);                       \
    float r0_ = __shfl_down_sync(FULLMASK, Ab[PAR].x, 1);                      \
    float r1_ = __shfl_down_sync(FULLMASK, Ab[PAR].y, 1);                      \
    if (lane == 0)  { l0_ = LFb[PAR].x; l1_ = LFb[PAR].y; }                    \
    if (lane == 31) { r0_ = RFb[PAR].x; r1_ = RFb[PAR].y; }                    \
    p[0]  = pk(l0_, l1_);            p[1]  = pk(l1_, Ab[PAR].x);               \
    p[2]  = pk(Ab[PAR].x, Ab[PAR].y); p[3] = pk(Ab[PAR].y, Ab[PAR].z);         \
    p[4]  = pk(Ab[PAR].z, Ab[PAR].w); p[5] = pk(Ab[PAR].w, Bb[PAR].x);         \
    p[6]  = pk(Bb[PAR].x, Bb[PAR].y); p[7] = pk(Bb[PAR].y, Bb[PAR].z);         \
    p[8]  = pk(Bb[PAR].z, Bb[PAR].w); p[9] = pk(Bb[PAR].w, r0_);               \
    p[10] = pk(r0_, r1_);                                                      \
} while (0)

// One step s = sb + I (sb multiple of 10 -> I%5 slot, I&1 parity compile-time):
//   prefetch row s+2 into buf[s&1]; FMA row s (in p); store row s-4;
//   pack row s+1 (in buf[(s+1)&1]) into p.
#define STEP(I) do {                                                           \
    const int s_ = sb + (I);                                                   \
    LOADROW(s_ + 2, ((I) & 1));                                                \
    accstep<((I) % 5)>(acc, wp, p);                                            \
    if (s_ >= 4) {                                                             \
        float r0,r1,r2,r3,r4,r5,r6,r7;                                         \
        upk(acc[((I)+1)%5][0], r0, r1);                                        \
        upk(acc[((I)+1)%5][1], r2, r3);                                        \
        upk(acc[((I)+1)%5][2], r4, r5);                                        \
        upk(acc[((I)+1)%5][3], r6, r7);                                        \
        float* op_ = Oc + (size_t)(Y0 + s_ - 4) * IMG + x0;                    \
        *reinterpret_cast<float4*>(op_)     = make_float4(r0,r1,r2,r3);        \
        *reinterpret_cast<float4*>(op_ + 4) = make_float4(r4,r5,r6,r7);        \
    }                                                                          \
    acc[((I)+1)%5][0] = 0ull; acc[((I)+1)%5][1] = 0ull;                        \
    acc[((I)+1)%5][2] = 0ull; acc[((I)+1)%5][3] = 0ull;                        \
    PACKROW(((I)+1) & 1);                                                      \
} while (0)

    // prologue: rows 0,1 into buffers; pack row 0
    LOADROW(0, 0);
    LOADROW(1, 1);
    PACKROW(0);

    // 20 steps in unroll-10 blocks (sb = 0, 10)
    #pragma unroll 1
    for (int sb = 0; sb < NSTEP; sb += 10) {
        STEP(0); STEP(1); STEP(2); STEP(3); STEP(4);
        STEP(5); STEP(6); STEP(7); STEP(8); STEP(9);
    }

#undef STEP
#undef PACKROW
#undef LOADROW
}

extern "C" void kernel_launch(void* const* d_in, const int* in_sizes, int n_in,
                              void* d_out, int out_size)
{
    const float* X  = (const float*)d_in[0];
    const float* Kw = (const float*)d_in[1];
    float* Out      = (float*)d_out;

    dim3 grid(2, IMG / R / 4, 128);   // 2 x-halves, 8 strip-groups, 128 planes = 2048 CTAs
    dim3 block(32, 4);                // 4 warps, each owns one 256x16 strip
    conv5x5_kernel<<<grid, block>>>(X, Kw, Out);
}